// round 11
// baseline (speedup 1.0000x reference)
#include <cuda_runtime.h>
#include <cuda_bf16.h>
#include <cstdint>

#define NROWS 65536
#define D 64
#define K 1024
#define NCTAS 296
#define SWPC 3                    // scalar warps per CTA (wid 5..7)
#define SSTRIPS (NCTAS * SWPC)    // 888 scalar strips
#define TSTRIPS (2048 - SSTRIPS)  // 1160 tensor strips (rows 0..37119)
#define NSTRIPS 2048
#define TAU 2.5e-4f
#define RW 8

// Static scratch (no allocations). g_pool/g_done start 0; reset by last rescore block.
__device__ int    g_pool;
__device__ int    g_done;
__device__ uint4  g_emb_perm[K * 8];   // t-major permuted bf16 codebook, 128B/entry
__device__ float  g_ee[K];
__device__ double g_part[NSTRIPS];
__device__ double g_part2[NSTRIPS];
__device__ int    g_rcnt[NSTRIPS];
__device__ int    g_rrows[NSTRIPS * 32];

__device__ __forceinline__ uint32_t pack_bf16x2(float a, float b) {
    __nv_bfloat162 h = __floats2bfloat162_rn(a, b);
    return *(uint32_t*)&h;
}
__device__ __forceinline__ void mma16816(float& c0, float& c1, float& c2, float& c3,
                                         uint32_t a0, uint32_t a1, uint32_t a2, uint32_t a3,
                                         uint32_t b0, uint32_t b1) {
    asm volatile("mma.sync.aligned.m16n8k16.row.col.f32.bf16.bf16.f32 "
                 "{%0,%1,%2,%3}, {%4,%5,%6,%7}, {%8,%9}, {%0,%1,%2,%3};"
                 : "+f"(c0), "+f"(c1), "+f"(c2), "+f"(c3)
                 : "r"(a0), "r"(a1), "r"(a2), "r"(a3), "r"(b0), "r"(b1));
}
__device__ __forceinline__ float packd(float d, uint32_t e) {
    return __uint_as_float((__float_as_uint(d) & 0xFFFFFC00u) | e);
}
__device__ __forceinline__ void upd(float& m1, float& m2, float f) {
    float mx = fmaxf(m1, f);
    m1 = fminf(m1, f);
    m2 = fminf(m2, mx);
}
__device__ __forceinline__ void red4(float& m1, float& m2) {
    #pragma unroll
    for (int off = 1; off <= 2; off <<= 1) {
        float om1 = __shfl_xor_sync(0xffffffffu, m1, off);
        float om2 = __shfl_xor_sync(0xffffffffu, m2, off);
        m2 = fminf(fminf(m2, om2), fmaxf(m1, om1));
        m1 = fminf(m1, om1);
    }
}

__global__ void vq_pre_kernel(const float* __restrict__ emb) {
    int k = blockIdx.x * blockDim.x + threadIdx.x;
    if (k < K) {
        const float4* e = (const float4*)(emb + k * D);
        float s = 0.f;
        uint32_t p[32];
        #pragma unroll
        for (int j = 0; j < 16; ++j) {
            float4 v = e[j];
            s += v.x * v.x; s += v.y * v.y; s += v.z * v.z; s += v.w * v.w;
            p[2 * j]     = pack_bf16x2(v.x, v.y);
            p[2 * j + 1] = pack_bf16x2(v.z, v.w);
        }
        g_ee[k] = s;
        uint4* dst = g_emb_perm + (size_t)k * 8;
        #pragma unroll
        for (int t = 0; t < 4; ++t) {
            dst[t * 2]     = make_uint4(p[t], p[t + 4], p[t + 8],  p[t + 12]);
            dst[t * 2 + 1] = make_uint4(p[t + 16], p[t + 20], p[t + 24], p[t + 28]);
        }
    }
}

// ---------- tensor strip (R9-verified core; B via uniform global loads) ----------
__device__ void tensor_strip(int s, int wid, float* s_m1, float* s_m2,
                             const float* __restrict__ z,
                             const float* __restrict__ emb,
                             float* __restrict__ out) {
    const int lane = threadIdx.x & 31;
    const int g = lane >> 2, t = lane & 3;
    const int base = s * 32;

    uint32_t A[2][4][4];
    #pragma unroll
    for (int tl = 0; tl < 2; ++tl) {
        const float* r0 = z + (size_t)(base + tl * 16 + g) * D;
        const float* r1 = r0 + 8 * D;
        #pragma unroll
        for (int ks = 0; ks < 4; ++ks) {
            int kb = ks * 16 + 2 * t;
            float2 u0 = *(const float2*)(r0 + kb);
            float2 u1 = *(const float2*)(r1 + kb);
            float2 u2 = *(const float2*)(r0 + kb + 8);
            float2 u3 = *(const float2*)(r1 + kb + 8);
            A[tl][ks][0] = pack_bf16x2(u0.x, u0.y);
            A[tl][ks][1] = pack_bf16x2(u1.x, u1.y);
            A[tl][ks][2] = pack_bf16x2(u2.x, u2.y);
            A[tl][ks][3] = pack_bf16x2(u3.x, u3.y);
        }
    }

    float u0m1 = 3.0e38f, u0m2 = 3.0e38f, l0m1 = 3.0e38f, l0m2 = 3.0e38f;
    float u1m1 = 3.0e38f, u1m2 = 3.0e38f, l1m1 = 3.0e38f, l1m2 = 3.0e38f;

    for (int nt = 0; nt < K / 8; ++nt) {
        const int nb = nt * 8;
        const uint4* bp = g_emb_perm + (size_t)(nb + g) * 8 + t * 2;
        uint4 q0 = __ldg(bp);
        uint4 q1 = __ldg(bp + 1);

        float c00 = 0.f, c01 = 0.f, c02 = 0.f, c03 = 0.f;
        float c10 = 0.f, c11 = 0.f, c12 = 0.f, c13 = 0.f;
        mma16816(c00, c01, c02, c03, A[0][0][0], A[0][0][1], A[0][0][2], A[0][0][3], q0.x, q0.y);
        mma16816(c10, c11, c12, c13, A[1][0][0], A[1][0][1], A[1][0][2], A[1][0][3], q0.x, q0.y);
        mma16816(c00, c01, c02, c03, A[0][1][0], A[0][1][1], A[0][1][2], A[0][1][3], q0.z, q0.w);
        mma16816(c10, c11, c12, c13, A[1][1][0], A[1][1][1], A[1][1][2], A[1][1][3], q0.z, q0.w);
        mma16816(c00, c01, c02, c03, A[0][2][0], A[0][2][1], A[0][2][2], A[0][2][3], q1.x, q1.y);
        mma16816(c10, c11, c12, c13, A[1][2][0], A[1][2][1], A[1][2][2], A[1][2][3], q1.x, q1.y);
        mma16816(c00, c01, c02, c03, A[0][3][0], A[0][3][1], A[0][3][2], A[0][3][3], q1.z, q1.w);
        mma16816(c10, c11, c12, c13, A[1][3][0], A[1][3][1], A[1][3][2], A[1][3][3], q1.z, q1.w);

        float2 ee = __ldg((const float2*)(g_ee + nb + 2 * t));
        uint32_t e0 = nb + 2 * t, e1 = e0 + 1;
        upd(u0m1, u0m2, packd(fmaf(-2.f, c00, ee.x), e0));
        upd(u0m1, u0m2, packd(fmaf(-2.f, c01, ee.y), e1));
        upd(l0m1, l0m2, packd(fmaf(-2.f, c02, ee.x), e0));
        upd(l0m1, l0m2, packd(fmaf(-2.f, c03, ee.y), e1));
        upd(u1m1, u1m2, packd(fmaf(-2.f, c10, ee.x), e0));
        upd(u1m1, u1m2, packd(fmaf(-2.f, c11, ee.y), e1));
        upd(l1m1, l1m2, packd(fmaf(-2.f, c12, ee.x), e0));
        upd(l1m1, l1m2, packd(fmaf(-2.f, c13, ee.y), e1));
    }

    red4(u0m1, u0m2); red4(l0m1, l0m2); red4(u1m1, u1m2); red4(l1m1, l1m2);
    float* m1 = s_m1 + wid * 32;
    float* m2 = s_m2 + wid * 32;
    if (t == 0) {
        m1[g]      = u0m1; m2[g]      = u0m2;
        m1[g + 8]  = l0m1; m2[g + 8]  = l0m2;
        m1[g + 16] = u1m1; m2[g + 16] = u1m2;
        m1[g + 24] = l1m1; m2[g + 24] = l1m2;
    }
    __syncwarp();

    const int row = base + lane;
    float rm1 = m1[lane], rm2 = m2[lane];
    int   idx1 = (int)(__float_as_uint(rm1) & 1023u);
    bool  tie = (rm2 - rm1 < TAU);
    uint32_t mask = __ballot_sync(0xffffffffu, tie);

    double lacc = 0.0;
    if (tie) {
        int pos = __popc(mask & ((1u << lane) - 1u));
        g_rrows[s * 32 + pos] = row;
    } else {
        const float4* zp = (const float4*)z + (size_t)row * 16;
        const float4* eb = (const float4*)emb + (size_t)idx1 * 16;
        float4* op = (float4*)out + (size_t)row * 16;
        #pragma unroll
        for (int j = 0; j < 16; ++j) {
            float4 q = eb[j];
            float4 zv = zp[j];
            op[j] = q;
            float dx = q.x - zv.x, dy = q.y - zv.y;
            float dz = q.z - zv.z, dw = q.w - zv.w;
            lacc += (double)dx * dx + (double)dy * dy
                  + (double)dz * dz + (double)dw * dw;
        }
    }
    #pragma unroll
    for (int off = 16; off; off >>= 1)
        lacc += __shfl_down_sync(0xffffffffu, lacc, off);
    if (lane == 0) {
        g_rcnt[s] = __popc(mask);
        g_part[s] = lacc;
    }
}

__global__ __launch_bounds__(256, 2)
void vq_main_kernel(const float* __restrict__ z,
                    const float* __restrict__ emb,
                    float* __restrict__ out) {
    __shared__ float s_tile[128 * 64];           // 128 fp32 entries = 32 KB (FIXED size)
    __shared__ float s_ee2[128];
    __shared__ float s_m1[8 * 32], s_m2[8 * 32];

    const int tid  = threadIdx.x;
    const int wid  = tid >> 5;
    const int lane = tid & 31;

    if (wid >= 8 - SWPC) {
        // ---------- SCALAR: exact fp32 (R1 math), shared smem tile, no rescore ----------
        const int sw    = wid - (8 - SWPC);
        const int strip = TSTRIPS + blockIdx.x * SWPC + sw;
        const int row   = strip * 32 + lane;
        const int sidx  = sw * 32 + lane;            // 0..95

        float4 zr[16];
        const float4* zp = (const float4*)z + (size_t)row * 16;
        #pragma unroll
        for (int j = 0; j < 16; ++j) zr[j] = zp[j];

        float zz = 0.f;
        #pragma unroll
        for (int j = 0; j < 16; ++j) {
            zz += zr[j].x * zr[j].x; zz += zr[j].y * zr[j].y;
            zz += zr[j].z * zr[j].z; zz += zr[j].w * zr[j].w;
        }

        float dmin = 3.4e38f;
        int   best = 0;

        for (int ch = 0; ch < 8; ++ch) {
            asm volatile("bar.sync 1, 96;" ::: "memory");
            for (int f = sidx; f < 128 * 16; f += 96)
                ((float4*)s_tile)[f] = ((const float4*)emb)[(size_t)ch * 128 * 16 + f];
            for (int f = sidx; f < 128; f += 96)
                s_ee2[f] = g_ee[ch * 128 + f];
            asm volatile("bar.sync 1, 96;" ::: "memory");

            for (int e = 0; e < 128; ++e) {
                const float4* ev = (const float4*)s_tile + e * 16;
                float a0 = 0.f, a1 = 0.f, a2 = 0.f, a3 = 0.f;
                #pragma unroll
                for (int j = 0; j < 16; j += 2) {
                    float4 v0 = ev[j], v1 = ev[j + 1];
                    a0 += zr[j].x * v0.x;     a0 += zr[j].y * v0.y;
                    a1 += zr[j].z * v0.z;     a1 += zr[j].w * v0.w;
                    a2 += zr[j + 1].x * v1.x; a2 += zr[j + 1].y * v1.y;
                    a3 += zr[j + 1].z * v1.z; a3 += zr[j + 1].w * v1.w;
                }
                float ze = (a0 + a1) + (a2 + a3);
                float d = (zz - 2.0f * ze) + s_ee2[e];
                if (d < dmin) { dmin = d; best = ch * 128 + e; }   // first-min
            }
        }

        double lacc = 0.0;
        const float4* eb = (const float4*)emb + (size_t)best * 16;
        float4* op = (float4*)out + (size_t)row * 16;
        #pragma unroll
        for (int j = 0; j < 16; ++j) {
            float4 q = eb[j];
            op[j] = q;
            float dx = q.x - zr[j].x, dy = q.y - zr[j].y;
            float dz = q.z - zr[j].z, dw = q.w - zr[j].w;
            lacc += (double)dx * dx + (double)dy * dy
                  + (double)dz * dz + (double)dw * dw;
        }
        #pragma unroll
        for (int off = 16; off; off >>= 1)
            lacc += __shfl_down_sync(0xffffffffu, lacc, off);
        if (lane == 0) {
            g_rcnt[strip] = 0;
            g_part[strip] = lacc;
        }
        // Fall through: help drain the tensor pool.
    }

    // ---------- TENSOR POOL: warps 0-4 immediately; scalar warps after ----------
    for (;;) {
        int s;
        if (lane == 0) s = atomicAdd(&g_pool, 1);
        s = __shfl_sync(0xffffffffu, s, 0);
        if (s >= TSTRIPS) break;
        tensor_strip(s, wid, s_m1, s_m2, z, emb, out);
    }
}

// Exact fp32 rescan (R1 arithmetic) for near-tie tensor rows + fused final reduce.
__global__ __launch_bounds__(256)
void vq_rescore_fin_kernel(const float* __restrict__ z,
                           const float* __restrict__ emb,
                           float* __restrict__ out, int out_size) {
    __shared__ float s_emb[128 * 69];
    __shared__ float s_zrow[RW * 64];
    __shared__ int   s_rows[RW];
    __shared__ double s_red[8];
    __shared__ int   s_last;

    const int b = blockIdx.x;
    const int n = g_rcnt[b];
    const int tid = threadIdx.x;
    const int w = tid >> 5, l = tid & 31;

    double wacc = 0.0;
    for (int base = 0; base < n; base += RW) {
        __syncthreads();
        if (tid < RW)
            s_rows[tid] = (base + tid < n) ? g_rrows[b * 32 + base + tid] : -1;
        __syncthreads();
        if (tid < RW * 16) {
            int rw = tid >> 4, j = tid & 15;
            int r = s_rows[rw];
            if (r >= 0)
                *(float4*)(s_zrow + rw * 64 + j * 4) = ((const float4*)z)[(size_t)r * 16 + j];
        }
        __syncthreads();

        int myrow = s_rows[w];
        float zz = 0.f;
        if (myrow >= 0)
            for (int i = 0; i < 64; ++i) { float v = s_zrow[w * 64 + i]; zz += v * v; }

        float dmin = 3.4e38f;
        int   bestk = 0;

        for (int tt = 0; tt < K / 128; ++tt) {
            __syncthreads();
            for (int f = tid; f < 128 * 16; f += 256) {
                int e = f >> 4, j = f & 15;
                float4 v = ((const float4*)emb)[(size_t)(tt * 128 + e) * 16 + j];
                float* dst = s_emb + e * 69 + j * 4;
                dst[0] = v.x; dst[1] = v.y; dst[2] = v.z; dst[3] = v.w;
            }
            __syncthreads();
            if (myrow >= 0) {
                #pragma unroll
                for (int q = 0; q < 4; ++q) {
                    int el = q * 32 + l;
                    const float* e = s_emb + el * 69;
                    float ze = 0.f;
                    for (int i = 0; i < 64; ++i) ze += s_zrow[w * 64 + i] * e[i];
                    int ge = tt * 128 + el;
                    float d = (zz - 2.0f * ze) + g_ee[ge];
                    if (d < dmin) { dmin = d; bestk = ge; }
                }
            }
        }

        #pragma unroll
        for (int off = 16; off; off >>= 1) {
            float od = __shfl_down_sync(0xffffffffu, dmin, off);
            int   oi = __shfl_down_sync(0xffffffffu, bestk, off);
            if (od < dmin || (od == dmin && oi < bestk)) { dmin = od; bestk = oi; }
        }

        if (myrow >= 0 && l == 0) {
            const float4* eb = (const float4*)emb + (size_t)bestk * 16;
            float4* op = (float4*)out + (size_t)myrow * 16;
            for (int j = 0; j < 16; ++j) {
                float4 q = eb[j];
                float zx = s_zrow[w * 64 + j * 4 + 0];
                float zy = s_zrow[w * 64 + j * 4 + 1];
                float zzv = s_zrow[w * 64 + j * 4 + 2];
                float zw = s_zrow[w * 64 + j * 4 + 3];
                op[j] = q;
                float dx = q.x - zx, dy = q.y - zy, dz = q.z - zzv, dw = q.w - zw;
                wacc += (double)dx * dx + (double)dy * dy
                      + (double)dz * dz + (double)dw * dw;
            }
        }
    }
    __syncthreads();
    if (l == 0) s_red[w] = wacc;
    __syncthreads();
    if (tid == 0) {
        double s2 = 0.0;
        #pragma unroll
        for (int i = 0; i < 8; ++i) s2 += s_red[i];
        g_part2[b] = s2;
        __threadfence();
        s_last = (atomicAdd(&g_done, 1) == gridDim.x - 1);
    }
    __syncthreads();
    if (s_last) {
        double v = 0.0;
        for (int i = tid; i < NSTRIPS; i += 256)
            v += g_part[i] + g_part2[i];
        #pragma unroll
        for (int off = 16; off; off >>= 1)
            v += __shfl_down_sync(0xffffffffu, v, off);
        if (l == 0) s_red[w] = v;
        __syncthreads();
        if (tid == 0) {
            double s = 0.0;
            #pragma unroll
            for (int i = 0; i < 8; ++i) s += s_red[i];
            if (out_size > NROWS * D)
                out[NROWS * D] = (float)(1.25 * s / (double)((long long)NROWS * D));
            g_done = 0;
            g_pool = 0;   // reset for next graph replay
        }
    }
}

extern "C" void kernel_launch(void* const* d_in, const int* in_sizes, int n_in,
                              void* d_out, int out_size) {
    const float* z   = (const float*)d_in[0];
    const float* emb = (const float*)d_in[1];
    if (n_in >= 2 && in_sizes[0] == K * D && in_sizes[1] == NROWS * D) {
        z   = (const float*)d_in[1];
        emb = (const float*)d_in[0];
    }
    float* out = (float*)d_out;

    vq_pre_kernel<<<8, 128>>>(emb);
    vq_main_kernel<<<NCTAS, 256>>>(z, emb, out);
    vq_rescore_fin_kernel<<<NSTRIPS, 256>>>(z, emb, out, out_size);
}